// round 6
// baseline (speedup 1.0000x reference)
#include <cuda_runtime.h>
#include <stdint.h>

#define BB 2
#define NN 2048
#define TK 8
#define NF 64
#define NNODES (BB*NN)
#define NE (NNODES*TK)

// ---------------- packed-fp32 (FFMA2) helpers ----------------
#define FMA2(acc, a, b) \
    asm("fma.rn.f32x2 %0, %1, %2, %0;" : "+l"(acc) : "l"(a), "l"(b))
#define DUP2(d, v) \
    asm("mov.b64 %0, {%1, %1};" : "=l"(d) : "f"(v))
#define PACK2(d, lo, hi) \
    asm("mov.b64 %0, {%1, %2};" : "=l"(d) : "f"(lo), "f"(hi))
#define UNPK2(lo, hi, v) \
    asm("mov.b64 {%0, %1}, %2;" : "=f"(lo), "=f"(hi) : "l"(v))

// ---------------- device scratch ----------------
__device__ int   g_send[NE];          // sender idx within batch, -1 = invalid
__device__ float g_A[NE*NF];          // rel_enc @ rp_w[0:64] + rp_b (hoisted)
__device__ float g_q[NNODES*NF];      // pp_w[0:64]^T p_enc + pp_b
__device__ float g_UV[NNODES*128];    // per-step: [U | V] = eff @ [Wr | Ws]
__device__ float g_eff0[NNODES*NF];
__device__ float g_eff1[NNODES*NF];

// runtime mask dtype detection (mask[0] is true in-dataset):
//  u8 storage -> 0x01010101 ; f32 -> 0x3f800000 ; else int32
__device__ __forceinline__ unsigned char mask_elem(const unsigned char* p, int i) {
    unsigned w0 = *(const unsigned*)p;
    if (w0 == 0x01010101u) return p[i] != 0;
    if (w0 == 0x3f800000u) return ((const float*)p)[i] != 0.f;
    return ((const int*)p)[i] != 0;
}

// ---------------- K1: edge construction (8-NN with threshold) ----------------
__global__ __launch_bounds__(256) void k_edges(
    const float* __restrict__ states,
    const unsigned char* __restrict__ mask_raw,
    const unsigned char* __restrict__ tmask_raw)
{
    __shared__ float s_st[NN*3];
    __shared__ unsigned char s_m[NN];
    int b  = blockIdx.x / (NN/8);
    int i0 = (blockIdx.x % (NN/8)) * 8;
    const float* stb = states + (size_t)b*NN*3;
    for (int t = threadIdx.x; t < NN*3; t += 256) s_st[t] = stb[t];
    for (int t = threadIdx.x; t < NN;   t += 256)
        s_m[t] = mask_elem(mask_raw, b*NN + t);
    __syncthreads();

    const float TH2 = 0.12f * 0.12f;

    int w = threadIdx.x >> 5, lane = threadIdx.x & 31;
    int i = i0 + w;
    int node = b*NN + i;
    bool recv_ok = mask_elem(mask_raw, node) && !mask_elem(tmask_raw, node);

    unsigned long long keys[TK];
#pragma unroll
    for (int k = 0; k < TK; k++) keys[k] = ~0ULL;

    if (recv_ok) {
        float xi = s_st[i*3+0], yi = s_st[i*3+1], zi = s_st[i*3+2];
        unsigned long long curmax = ~0ULL; int maxslot = 0;
        for (int j = lane; j < NN; j += 32) {
            float dx = xi - s_st[j*3+0];
            float dy = yi - s_st[j*3+1];
            float dz = zi - s_st[j*3+2];
            float d2 = fmaf(dx, dx, fmaf(dy, dy, dz*dz));
            if (!s_m[j]) d2 = 1e10f;
            unsigned long long key =
                ((unsigned long long)__float_as_uint(d2) << 32) | (unsigned)j;
            if (key < curmax) {
                keys[maxslot] = key;
                curmax = keys[0]; maxslot = 0;
#pragma unroll
                for (int k = 1; k < TK; k++)
                    if (keys[k] > curmax) { curmax = keys[k]; maxslot = k; }
            }
        }
    }

#pragma unroll 1
    for (int r = 0; r < TK; r++) {
        unsigned long long mymin = keys[0]; int mslot = 0;
#pragma unroll
        for (int k = 1; k < TK; k++)
            if (keys[k] < mymin) { mymin = keys[k]; mslot = k; }
        unsigned long long v = mymin;
#pragma unroll
        for (int off = 16; off; off >>= 1) {
            unsigned long long o = __shfl_down_sync(0xffffffffu, v, off);
            if (o < v) v = o;
        }
        v = __shfl_sync(0xffffffffu, v, 0);
        if (v == mymin && v != ~0ULL) keys[mslot] = ~0ULL;
        if (lane == 0) {
            float d2 = __uint_as_float((unsigned)(v >> 32));
            int j = (int)(v & 0xffffffffULL);
            bool valid = (v != ~0ULL) && (d2 < TH2);
            g_send[node*TK + r] = valid ? j : -1;
        }
    }
}

// ---------------- K2: particle encoder + hoisted pp_w top-half --------------
__global__ __launch_bounds__(256) void k_penc(
    const float* __restrict__ s_delta, const float* __restrict__ a_cur,
    const float* __restrict__ pe_w1, const float* __restrict__ pe_b1,
    const float* __restrict__ pe_w2, const float* __restrict__ pe_b2,
    const float* __restrict__ pp_w,  const float* __restrict__ pp_b)
{
    __shared__ float w1[12*NF], w2[NF*NF], wq[NF*NF];
    __shared__ float b1[NF], b2[NF], bq[NF];
    __shared__ float pin[4][12];
    __shared__ float hb[4][NF];
    for (int t = threadIdx.x; t < 12*NF; t += 256) w1[t] = pe_w1[t];
    for (int t = threadIdx.x; t < NF*NF; t += 256) w2[t] = pe_w2[t];
    for (int t = threadIdx.x; t < NF*NF; t += 256) wq[t] = pp_w[t]; // rows 0..63
    if (threadIdx.x < NF) {
        b1[threadIdx.x] = pe_b1[threadIdx.x];
        b2[threadIdx.x] = pe_b2[threadIdx.x];
        bq[threadIdx.x] = pp_b[threadIdx.x];
    }
    __syncthreads();

    int g = threadIdx.x >> 6;
    int c = threadIdx.x & 63;
    for (int it = 0; it < 4; ++it) {
        int node = blockIdx.x*16 + it*4 + g;
        int b = node / NN, n = node % NN;
        if (c < 12)
            pin[g][c] = (c < 9) ? s_delta[((size_t)b*9 + c)*NN + n]
                                : a_cur[b*NN + n];
        __syncthreads();
        float acc = b1[c];
#pragma unroll
        for (int r = 0; r < 12; r++) acc = fmaf(pin[g][r], w1[r*NF+c], acc);
        hb[g][c] = fmaxf(acc, 0.f);
        __syncthreads();
        acc = b2[c];
#pragma unroll 16
        for (int r = 0; r < NF; r++) acc = fmaf(hb[g][r], w2[r*NF+c], acc);
        float pe = fmaxf(acc, 0.f);
        g_eff0[(size_t)node*NF + c] = pe;
        __syncthreads();
        hb[g][c] = pe;
        __syncthreads();
        acc = bq[c];
#pragma unroll 16
        for (int r = 0; r < NF; r++) acc = fmaf(hb[g][r], wq[r*NF+c], acc);
        g_q[(size_t)node*NF + c] = acc;
        __syncthreads();
    }
}

// ---------------- K3: relation encoder, 4 threads/edge ----------------------
// 256 threads = 64 edges x 4 col-parts (16 cols each). grid = NE/64 = 512.
// sW: one layer's 64x64 weights, bank-padded: elem (r,c) at
//     r*84 + (c>>4)*20 + (c&15). sh: per-edge h duplicated f32x2, stride 132.
__device__ __forceinline__ void rel_store_h(
    float* sh, int el, int cbase, unsigned long long* acc2)
{
#pragma unroll
    for (int p = 0; p < 4; p++) {
        float a0,a1,a2,a3;
        UNPK2(a0, a1, acc2[2*p]);
        UNPK2(a2, a3, acc2[2*p+1]);
        a0 = fmaxf(a0, 0.f); a1 = fmaxf(a1, 0.f);
        a2 = fmaxf(a2, 0.f); a3 = fmaxf(a3, 0.f);
        float* dst = &sh[el*132 + 2*cbase + 8*p];
        *(float4*)dst       = make_float4(a0, a0, a1, a1);
        *(float4*)(dst + 4) = make_float4(a2, a2, a3, a3);
    }
}

__global__ __launch_bounds__(256) void k_rel(
    const float* __restrict__ states, const float* __restrict__ a_cur,
    const float* __restrict__ re_w1, const float* __restrict__ re_b1,
    const float* __restrict__ re_w2, const float* __restrict__ re_b2,
    const float* __restrict__ re_w3, const float* __restrict__ re_b3,
    const float* __restrict__ rp_w,  const float* __restrict__ rp_b)
{
    extern __shared__ float dsm[];
    float* sW  = dsm;                 // 64*84 = 5376
    float* sh  = dsm + 5376;          // 64*132 = 8448
    float* sw1 = dsm + 5376 + 8448;   // 320
    float* sb1 = sw1 + 320;           // 64
    float* sb  = sb1 + 64;            // 64

    for (int t = threadIdx.x; t < 4096; t += 256) {
        int r = t >> 6, c = t & 63;
        sW[r*84 + (c>>4)*20 + (c&15)] = re_w2[t];
    }
    for (int t = threadIdx.x; t < 320; t += 256) sw1[t] = re_w1[t];
    if (threadIdx.x < 64) {
        sb1[threadIdx.x] = re_b1[threadIdx.x];
        sb [threadIdx.x] = re_b2[threadIdx.x];
    }
    __syncthreads();

    int el = threadIdx.x >> 2, part = threadIdx.x & 3;
    int cbase = part * 16;
    int e = blockIdx.x*64 + el;
    int node = e >> 3;
    int b = node >> 11, i = node & (NN-1);
    int j = g_send[e];
    int jj = j < 0 ? 0 : j;

    float rin[5];
    rin[0] = a_cur[b*NN + i];
    rin[1] = a_cur[b*NN + jj];
#pragma unroll
    for (int d = 0; d < 3; d++)
        rin[2+d] = states[((size_t)b*NN + i)*3 + d]
                 - states[((size_t)b*NN + jj)*3 + d];

    unsigned long long acc2[8];
    // ---- L1: 5 -> 64 (my 16 cols) ----
#pragma unroll
    for (int p = 0; p < 8; p++)
        PACK2(acc2[p], sb1[cbase + 2*p], sb1[cbase + 2*p + 1]);
#pragma unroll
    for (int r = 0; r < 5; r++) {
        unsigned long long xd; DUP2(xd, rin[r]);
        const float* wp = &sw1[r*64 + cbase];
        ulonglong2 wa = *(const ulonglong2*)(wp);
        ulonglong2 wb = *(const ulonglong2*)(wp + 8);
        FMA2(acc2[0], wa.x, xd); FMA2(acc2[1], wa.y, xd);
        FMA2(acc2[2], *(const unsigned long long*)(wp+4), xd);
        FMA2(acc2[3], *(const unsigned long long*)(wp+6), xd);
        FMA2(acc2[4], wb.x, xd); FMA2(acc2[5], wb.y, xd);
        FMA2(acc2[6], *(const unsigned long long*)(wp+12), xd);
        FMA2(acc2[7], *(const unsigned long long*)(wp+14), xd);
    }
    rel_store_h(sh, el, cbase, acc2);
    __syncthreads();

    // ---- L2 (re_w2,relu), L3 (re_w3,relu), L4 (rp_w[0:64]+rp_b, no relu) ---
#pragma unroll 1
    for (int L = 0; L < 3; L++) {
#pragma unroll
        for (int p = 0; p < 8; p++)
            PACK2(acc2[p], sb[cbase + 2*p], sb[cbase + 2*p + 1]);
#pragma unroll 8
        for (int r = 0; r < 64; r++) {
            unsigned long long hv =
                *(const unsigned long long*)&sh[el*132 + 2*r];
            const float* wp = &sW[r*84 + part*20];
            ulonglong2 wa = *(const ulonglong2*)(wp);
            ulonglong2 wb = *(const ulonglong2*)(wp + 4);
            ulonglong2 wc = *(const ulonglong2*)(wp + 8);
            ulonglong2 wd = *(const ulonglong2*)(wp + 12);
            FMA2(acc2[0], wa.x, hv); FMA2(acc2[1], wa.y, hv);
            FMA2(acc2[2], wb.x, hv); FMA2(acc2[3], wb.y, hv);
            FMA2(acc2[4], wc.x, hv); FMA2(acc2[5], wc.y, hv);
            FMA2(acc2[6], wd.x, hv); FMA2(acc2[7], wd.y, hv);
        }
        if (L < 2) {
            __syncthreads();   // all reads of sh/sW done
            rel_store_h(sh, el, cbase, acc2);
            const float* nw = (L == 0) ? re_w3 : rp_w;
            const float* nb = (L == 0) ? re_b3 : rp_b;
            for (int t = threadIdx.x; t < 4096; t += 256) {
                int r = t >> 6, c = t & 63;
                sW[r*84 + (c>>4)*20 + (c&15)] = nw[t];
            }
            if (threadIdx.x < 64) sb[threadIdx.x] = nb[threadIdx.x];
            __syncthreads();
        } else {
            float* dst = g_A + (size_t)e*64 + cbase;
#pragma unroll
            for (int p = 0; p < 4; p++) {
                float a0,a1,a2,a3;
                UNPK2(a0, a1, acc2[2*p]);
                UNPK2(a2, a3, acc2[2*p+1]);
                if (j < 0) { a0 = a1 = a2 = a3 = 0.f; }
                *(float4*)(dst + 4*p) = make_float4(a0, a1, a2, a3);
            }
        }
    }
}

// ---------------- K4a: UV = eff0 @ [Wr | Ws] (initial step only) ------------
#define SE 64
__global__ __launch_bounds__(128) void k_uv(const float* __restrict__ rp_w)
{
    const float* effin = g_eff0;
    extern __shared__ float dsm[];
    float* sW  = dsm;            // [64][128]
    float* sEd = dsm + 64*128;   // [64][SE]

    for (int t = threadIdx.x; t < 64*128; t += 128) {
        int r = t >> 7, c = t & 127;
        sW[t] = (c < 64) ? rp_w[(size_t)(64+r)*64 + c]
                         : rp_w[(size_t)(128+r)*64 + (c-64)];
    }
    int node0 = blockIdx.x * 32;
    {
        int n  = threadIdx.x >> 2;
        int cg = threadIdx.x & 3;
        const float* src = effin + (size_t)(node0 + n)*64 + cg*16;
#pragma unroll
        for (int m4 = 0; m4 < 4; m4++) {
            float4 v = *(const float4*)(src + m4*4);
            int c = cg*16 + m4*4;
            *(float2*)&sEd[(c+0)*SE + 2*n] = make_float2(v.x, v.x);
            *(float2*)&sEd[(c+1)*SE + 2*n] = make_float2(v.y, v.y);
            *(float2*)&sEd[(c+2)*SE + 2*n] = make_float2(v.z, v.z);
            *(float2*)&sEd[(c+3)*SE + 2*n] = make_float2(v.w, v.w);
        }
    }
    __syncthreads();

    int tc = threadIdx.x & 15;
    int tn = threadIdx.x >> 4;
    unsigned long long acc[4][4];
#pragma unroll
    for (int m = 0; m < 4; m++)
#pragma unroll
        for (int p = 0; p < 4; p++) acc[m][p] = 0ULL;

#pragma unroll 4
    for (int r = 0; r < 64; r++) {
        unsigned long long ev[4];
#pragma unroll
        for (int m = 0; m < 4; m++)
            ev[m] = *(const unsigned long long*)&sEd[r*SE + tn*8 + 2*m];
        ulonglong2 w01 = *(const ulonglong2*)&sW[r*128 + tc*8];
        ulonglong2 w23 = *(const ulonglong2*)&sW[r*128 + tc*8 + 4];
#pragma unroll
        for (int m = 0; m < 4; m++) {
            FMA2(acc[m][0], w01.x, ev[m]);
            FMA2(acc[m][1], w01.y, ev[m]);
            FMA2(acc[m][2], w23.x, ev[m]);
            FMA2(acc[m][3], w23.y, ev[m]);
        }
    }
#pragma unroll
    for (int m = 0; m < 4; m++) {
        int node = node0 + tn*4 + m;
        float x0,x1,x2,x3,x4,x5,x6,x7;
        UNPK2(x0,x1, acc[m][0]); UNPK2(x2,x3, acc[m][1]);
        UNPK2(x4,x5, acc[m][2]); UNPK2(x6,x7, acc[m][3]);
        float* dst = g_UV + (size_t)node*128 + tc*8;
        *(float4*)dst       = make_float4(x0,x1,x2,x3);
        *(float4*)(dst + 4) = make_float4(x4,x5,x6,x7);
    }
}

// ---------------- K4: fused prop step -------------------------------------
// Phase A: edge gather/aggregate + output GEMM -> effout (gmem + smem staged)
// Phase B: UV' = effout @ [Wr|Ws] for own 32 nodes (next step's input)
// grid = NNODES/32 = 128, 256 threads.
#define SA  66
#define SED 66
__global__ __launch_bounds__(256) void k_step(
    int which,
    const float* __restrict__ rp_w, const float* __restrict__ pp_w)
{
    const float* effin  = (which & 1) ? g_eff1 : g_eff0;
    float*       effout = (which & 1) ? g_eff0 : g_eff1;
    extern __shared__ float dsm[];
    float* sWp  = dsm;                    // 4096  (pp_w rows 64..127)
    float* sWrs = dsm + 4096;             // 64*192 = 12288, chunk-padded
    float* sAgg = dsm + 4096 + 12288;     // 64*SA = 4224
    float* sEd  = sAgg + 64*SA;           // 64*SED = 4224

    for (int t = threadIdx.x; t < 4096; t += 256) sWp[t] = pp_w[4096 + t];
    for (int t = threadIdx.x; t < 8192; t += 256) {
        int r = t >> 7, c = t & 127;
        float v = (c < 64) ? rp_w[(size_t)(64+r)*64 + c]
                           : rp_w[(size_t)(128+r)*64 + (c-64)];
        sWrs[r*192 + (c>>3)*12 + (c&7)] = v;
    }

    int w = threadIdx.x >> 5, l = threadIdx.x & 31;
    int node0 = blockIdx.x * 32;
    // --- Phase A1: per-edge gather + relu-sum ---
#pragma unroll 1
    for (int kk = 0; kk < 4; kk++) {
        int node = node0 + w*4 + kk;
        int bN = (node >= NN) ? NN : 0;
        float2 u = *(const float2*)&g_UV[(size_t)node*128 + 2*l];
        float s0 = 0.f, s1 = 0.f;
#pragma unroll
        for (int k = 0; k < TK; k++) {
            int j = g_send[node*TK + k];       // warp-uniform
            if (j >= 0) {
                float2 a = *(const float2*)&g_A[((size_t)node*TK + k)*64 + 2*l];
                float2 v = *(const float2*)&g_UV[(size_t)(bN + j)*128 + 64 + 2*l];
                s0 += fmaxf(a.x + u.x + v.x, 0.f);
                s1 += fmaxf(a.y + u.y + v.y, 0.f);
            }
        }
        int nl = node - node0;
        *(float2*)&sAgg[(2*l  )*SA + 2*nl] = make_float2(s0, s0);
        *(float2*)&sAgg[(2*l+1)*SA + 2*nl] = make_float2(s1, s1);
    }
    __syncthreads();

    // --- Phase A2: effout = relu(effin + q + agg @ Wp1) ---
    {
        int tc = threadIdx.x & 31;   // 2 cols
        int tn = threadIdx.x >> 5;   // 4 nodes
        unsigned long long acc[4] = {0ULL, 0ULL, 0ULL, 0ULL};
#pragma unroll 4
        for (int r = 0; r < 64; r++) {
            unsigned long long wv =
                *(const unsigned long long*)&sWp[r*64 + tc*2];
#pragma unroll
            for (int m = 0; m < 4; m++) {
                unsigned long long ev =
                    *(const unsigned long long*)&sAgg[r*SA + tn*8 + 2*m];
                FMA2(acc[m], wv, ev);
            }
        }
#pragma unroll
        for (int m = 0; m < 4; m++) {
            int node = node0 + tn*4 + m;
            int nl = tn*4 + m;
            float2 ein = *(const float2*)&effin[(size_t)node*64 + 2*tc];
            float2 q2  = *(const float2*)&g_q  [(size_t)node*64 + 2*tc];
            float o0, o1; UNPK2(o0, o1, acc[m]);
            o0 = fmaxf(o0 + ein.x + q2.x, 0.f);
            o1 = fmaxf(o1 + ein.y + q2.y, 0.f);
            *(float2*)&effout[(size_t)node*64 + 2*tc] = make_float2(o0, o1);
            *(float2*)&sEd[(2*tc  )*SED + 2*nl] = make_float2(o0, o0);
            *(float2*)&sEd[(2*tc+1)*SED + 2*nl] = make_float2(o1, o1);
        }
    }
    __syncthreads();

    // --- Phase B: UV' = effout @ [Wr|Ws] (for next step) ---
    {
        int tc2 = threadIdx.x & 15;  // 8 cols
        int tn2 = threadIdx.x >> 4;  // 2 nodes
        unsigned long long acc[2][4];
#pragma unroll
        for (int m = 0; m < 2; m++)
#pragma unroll
            for (int p = 0; p < 4; p++) acc[m][p] = 0ULL;
#pragma unroll 8
        for (int r = 0; r < 64; r++) {
            unsigned long long ev0 =
                *(const unsigned long long*)&sEd[r*SED + 4*tn2];
            unsigned long long ev1 =
                *(const unsigned long long*)&sEd[r*SED + 4*tn2 + 2];
            const float* wp = &sWrs[r*192 + tc2*12];
            ulonglong2 wa = *(const ulonglong2*)(wp);
            ulonglong2 wb = *(const ulonglong2*)(wp + 4);
            FMA2(acc[0][0], wa.x, ev0); FMA2(acc[0][1], wa.y, ev0);
            FMA2(acc[0][2], wb.x, ev0); FMA2(acc[0][3], wb.y, ev0);
            FMA2(acc[1][0], wa.x, ev1); FMA2(acc[1][1], wa.y, ev1);
            FMA2(acc[1][2], wb.x, ev1); FMA2(acc[1][3], wb.y, ev1);
        }
#pragma unroll
        for (int m = 0; m < 2; m++) {
            int node = node0 + 2*tn2 + m;
            float x0,x1,x2,x3,x4,x5,x6,x7;
            UNPK2(x0,x1, acc[m][0]); UNPK2(x2,x3, acc[m][1]);
            UNPK2(x4,x5, acc[m][2]); UNPK2(x6,x7, acc[m][3]);
            float* dst = g_UV + (size_t)node*128 + tc2*8;
            *(float4*)dst       = make_float4(x0,x1,x2,x3);
            *(float4*)(dst + 4) = make_float4(x4,x5,x6,x7);
        }
    }
}

// ---------------- K5: predictor + residual add ----------------
__global__ __launch_bounds__(256) void k_pred(
    const float* __restrict__ states,
    const float* __restrict__ pr_w1, const float* __restrict__ pr_b1,
    const float* __restrict__ pr_w2, const float* __restrict__ pr_b2,
    float* __restrict__ out)
{
    __shared__ float W1[NF*NF], b1[NF];
    __shared__ float W2[NF*3],  b2[3];
    __shared__ float ef[4][NF], hh[4][NF];
    for (int t = threadIdx.x; t < NF*NF; t += 256) W1[t] = pr_w1[t];
    for (int t = threadIdx.x; t < NF*3;  t += 256) W2[t] = pr_w2[t];
    if (threadIdx.x < NF) b1[threadIdx.x] = pr_b1[threadIdx.x];
    if (threadIdx.x < 3)  b2[threadIdx.x] = pr_b2[threadIdx.x];
    __syncthreads();

    int g = threadIdx.x >> 6;
    int c = threadIdx.x & 63;
    for (int it = 0; it < 4; ++it) {
        int node = blockIdx.x*16 + it*4 + g;
        ef[g][c] = g_eff1[(size_t)node*NF + c];
        __syncthreads();
        float acc = b1[c];
#pragma unroll 16
        for (int r = 0; r < NF; r++) acc = fmaf(ef[g][r], W1[r*NF+c], acc);
        hh[g][c] = fmaxf(acc, 0.f);
        __syncthreads();
        if (c < 3) {
            float p = b2[c];
#pragma unroll 16
            for (int r = 0; r < NF; r++) p = fmaf(hh[g][r], W2[r*3+c], p);
            out[(size_t)node*3 + c] = states[(size_t)node*3 + c] + p;
        }
        __syncthreads();
    }
}

// ---------------- launch ----------------
extern "C" void kernel_launch(void* const* d_in, const int* in_sizes, int n_in,
                              void* d_out, int out_size)
{
    const float* states  = (const float*)d_in[0];
    const float* a_cur   = (const float*)d_in[1];
    const float* s_delta = (const float*)d_in[2];
    const unsigned char* mask  = (const unsigned char*)d_in[3];
    const unsigned char* tmask = (const unsigned char*)d_in[4];
    int wbase = (n_in > 5 && in_sizes[5] == 1) ? 6 : 5;
    const float* pe_w1 = (const float*)d_in[wbase + 0];
    const float* pe_b1 = (const float*)d_in[wbase + 1];
    const float* pe_w2 = (const float*)d_in[wbase + 2];
    const float* pe_b2 = (const float*)d_in[wbase + 3];
    const float* re_w1 = (const float*)d_in[wbase + 4];
    const float* re_b1 = (const float*)d_in[wbase + 5];
    const float* re_w2 = (const float*)d_in[wbase + 6];
    const float* re_b2 = (const float*)d_in[wbase + 7];
    const float* re_w3 = (const float*)d_in[wbase + 8];
    const float* re_b3 = (const float*)d_in[wbase + 9];
    const float* rp_w  = (const float*)d_in[wbase + 10];
    const float* rp_b  = (const float*)d_in[wbase + 11];
    const float* pp_w  = (const float*)d_in[wbase + 12];
    const float* pp_b  = (const float*)d_in[wbase + 13];
    const float* pr_w1 = (const float*)d_in[wbase + 14];
    const float* pr_b1 = (const float*)d_in[wbase + 15];
    const float* pr_w2 = (const float*)d_in[wbase + 16];
    const float* pr_b2 = (const float*)d_in[wbase + 17];
    float* out = (float*)d_out;

    const int REL_SMEM  = (5376 + 8448 + 320 + 64 + 64) * 4;          // 57088
    const int UV_SMEM   = (64*128 + 64*SE) * 4;                       // 49152
    const int STEP_SMEM = (4096 + 64*192 + 64*SA + 64*SED) * 4;       // 99328
    static int attr_done = 0;
    if (!attr_done) {
        cudaFuncSetAttribute(k_rel,  cudaFuncAttributeMaxDynamicSharedMemorySize, REL_SMEM);
        cudaFuncSetAttribute(k_uv,   cudaFuncAttributeMaxDynamicSharedMemorySize, UV_SMEM);
        cudaFuncSetAttribute(k_step, cudaFuncAttributeMaxDynamicSharedMemorySize, STEP_SMEM);
        attr_done = 1;
    }

    k_edges<<<NNODES/8, 256>>>(states, mask, tmask);
    k_penc <<<NNODES/16, 256>>>(s_delta, a_cur, pe_w1, pe_b1, pe_w2, pe_b2,
                                pp_w, pp_b);
    k_rel  <<<NE/64, 256, REL_SMEM>>>(states, a_cur,
                                      re_w1, re_b1, re_w2, re_b2,
                                      re_w3, re_b3, rp_w, rp_b);
    k_uv   <<<NNODES/32, 128, UV_SMEM>>>(rp_w);
    k_step <<<NNODES/32, 256, STEP_SMEM>>>(0, rp_w, pp_w);  // eff0 -> eff1
    k_step <<<NNODES/32, 256, STEP_SMEM>>>(1, rp_w, pp_w);  // eff1 -> eff0
    k_step <<<NNODES/32, 256, STEP_SMEM>>>(2, rp_w, pp_w);  // eff0 -> eff1
    k_pred <<<NNODES/16, 256>>>(states, pr_w1, pr_b1, pr_w2, pr_b2, out);
}

// round 7
// speedup vs baseline: 1.2732x; 1.2732x over previous
#include <cuda_runtime.h>
#include <stdint.h>

#define BB 2
#define NN 2048
#define TK 8
#define NF 64
#define NNODES (BB*NN)
#define NE (NNODES*TK)
#define NBLK 128
#define SED 66
#define SA  66

// ---------------- packed-fp32 (FFMA2) helpers ----------------
#define FMA2(acc, a, b) \
    asm("fma.rn.f32x2 %0, %1, %2, %0;" : "+l"(acc) : "l"(a), "l"(b))
#define DUP2(d, v) \
    asm("mov.b64 %0, {%1, %1};" : "=l"(d) : "f"(v))
#define PACK2(d, lo, hi) \
    asm("mov.b64 %0, {%1, %2};" : "=l"(d) : "f"(lo), "f"(hi))
#define UNPK2(lo, hi, v) \
    asm("mov.b64 {%0, %1}, %2;" : "=f"(lo), "=f"(hi) : "l"(v))

// ---------------- device scratch ----------------
__device__ int   g_send[NE];
__device__ float g_A[NE*NF];
__device__ float g_q[NNODES*NF];
__device__ float g_UV[NNODES*128];
__device__ float g_eff0[NNODES*NF];
__device__ float g_eff1[NNODES*NF];
__device__ unsigned g_bar_cnt = 0;
__device__ unsigned g_bar_gen = 0;

// mask dtype detection (mask[0] true in-dataset)
__device__ __forceinline__ unsigned char mask_elem(const unsigned char* p, int i) {
    unsigned w0 = *(const unsigned*)p;
    if (w0 == 0x01010101u) return p[i] != 0;
    if (w0 == 0x3f800000u) return ((const float*)p)[i] != 0.f;
    return ((const int*)p)[i] != 0;
}

// grid-wide barrier: all NBLK blocks are wave-1 resident (NBLK <= 148 SMs).
// __threadfence (gpu scope) flushes L1 on sm_103a -> fresh cross-SM reads.
__device__ __forceinline__ void grid_bar() {
    __threadfence();
    __syncthreads();
    if (threadIdx.x == 0) {
        volatile unsigned* genp = &g_bar_gen;
        unsigned gen = *genp;
        if (atomicInc(&g_bar_cnt, NBLK - 1) == NBLK - 1) {
            atomicAdd(&g_bar_gen, 1);
        } else {
            while (*genp == gen) { }
        }
    }
    __syncthreads();
    __threadfence();
}

// h-chunk store for rel phase (row private to a 4-thread quad)
__device__ __forceinline__ void rel_store_h(
    float* myrow, int cbase, const unsigned long long* acc2)
{
#pragma unroll
    for (int p = 0; p < 4; p++) {
        float a0,a1,a2,a3;
        UNPK2(a0, a1, acc2[2*p]);
        UNPK2(a2, a3, acc2[2*p+1]);
        a0 = fmaxf(a0, 0.f); a1 = fmaxf(a1, 0.f);
        a2 = fmaxf(a2, 0.f); a3 = fmaxf(a3, 0.f);
        float* dst = myrow + 2*cbase + 8*p;
        *(float4*)dst       = make_float4(a0, a0, a1, a1);
        *(float4*)(dst + 4) = make_float4(a2, a2, a3, a3);
    }
}

// UV' = sEd(dup,transposed effout) @ [Wr|Ws] -> g_UV (own 32 nodes)
__device__ __forceinline__ void uv_from_sEd(
    const float* sWrs, const float* sEd, int node0, int tid)
{
    int tc2 = tid & 15;   // 8 cols of 128
    int tn2 = tid >> 4;   // 2 nodes each
    unsigned long long acc[2][4];
#pragma unroll
    for (int m = 0; m < 2; m++)
#pragma unroll
        for (int p = 0; p < 4; p++) acc[m][p] = 0ULL;
#pragma unroll 8
    for (int r = 0; r < 64; r++) {
        unsigned long long ev0 = *(const unsigned long long*)&sEd[r*SED + 4*tn2];
        unsigned long long ev1 = *(const unsigned long long*)&sEd[r*SED + 4*tn2 + 2];
        const float* wp = &sWrs[r*192 + tc2*12];
        ulonglong2 wa = *(const ulonglong2*)(wp);
        ulonglong2 wb = *(const ulonglong2*)(wp + 4);
        FMA2(acc[0][0], wa.x, ev0); FMA2(acc[0][1], wa.y, ev0);
        FMA2(acc[0][2], wb.x, ev0); FMA2(acc[0][3], wb.y, ev0);
        FMA2(acc[1][0], wa.x, ev1); FMA2(acc[1][1], wa.y, ev1);
        FMA2(acc[1][2], wb.x, ev1); FMA2(acc[1][3], wb.y, ev1);
    }
#pragma unroll
    for (int m = 0; m < 2; m++) {
        int node = node0 + 2*tn2 + m;
        float x0,x1,x2,x3,x4,x5,x6,x7;
        UNPK2(x0,x1, acc[m][0]); UNPK2(x2,x3, acc[m][1]);
        UNPK2(x4,x5, acc[m][2]); UNPK2(x6,x7, acc[m][3]);
        float* dst = g_UV + (size_t)node*128 + tc2*8;
        *(float4*)dst       = make_float4(x0,x1,x2,x3);
        *(float4*)(dst + 4) = make_float4(x4,x5,x6,x7);
    }
}

// =====================  THE persistent kernel  =====================
__global__ __launch_bounds__(256) void k_all(
    const float* __restrict__ states, const float* __restrict__ a_cur,
    const float* __restrict__ s_delta,
    const unsigned char* __restrict__ mask_raw,
    const unsigned char* __restrict__ tmask_raw,
    const float* __restrict__ pe_w1, const float* __restrict__ pe_b1,
    const float* __restrict__ pe_w2, const float* __restrict__ pe_b2,
    const float* __restrict__ re_w1, const float* __restrict__ re_b1,
    const float* __restrict__ re_w2, const float* __restrict__ re_b2,
    const float* __restrict__ re_w3, const float* __restrict__ re_b3,
    const float* __restrict__ rp_w,  const float* __restrict__ rp_b,
    const float* __restrict__ pp_w,  const float* __restrict__ pp_b,
    const float* __restrict__ pr_w1, const float* __restrict__ pr_b1,
    const float* __restrict__ pr_w2, const float* __restrict__ pr_b2,
    float* __restrict__ out)
{
    extern __shared__ float buf[];
    const int tid = threadIdx.x;
    const int node0 = blockIdx.x * 32;     // 32 owned nodes (same batch)
    const int bb = node0 >> 11;
    const int i0 = node0 & (NN-1);

    // ======== Phase E: edge construction (8-NN + threshold) ========
    {
        float* s_st = buf;                                    // 6144
        unsigned char* s_m = (unsigned char*)(buf + 6144);    // 2048 B
        const float* stb = states + (size_t)bb*NN*3;
        for (int t = tid; t < NN*3; t += 256) s_st[t] = stb[t];
        for (int t = tid; t < NN;   t += 256)
            s_m[t] = mask_elem(mask_raw, bb*NN + t);
        __syncthreads();

        const float TH2 = 0.12f * 0.12f;
        int w = tid >> 5, lane = tid & 31;
#pragma unroll 1
        for (int sub = 0; sub < 4; sub++) {
            int i = i0 + sub*8 + w;
            int node = bb*NN + i;
            bool recv_ok = (s_m[i] != 0) && !mask_elem(tmask_raw, node);

            unsigned long long keys[TK];
#pragma unroll
            for (int k = 0; k < TK; k++) keys[k] = ~0ULL;

            if (recv_ok) {
                float xi = s_st[i*3+0], yi = s_st[i*3+1], zi = s_st[i*3+2];
                unsigned long long curmax = ~0ULL; int maxslot = 0;
                for (int j = lane; j < NN; j += 32) {
                    float dx = xi - s_st[j*3+0];
                    float dy = yi - s_st[j*3+1];
                    float dz = zi - s_st[j*3+2];
                    float d2 = fmaf(dx, dx, fmaf(dy, dy, dz*dz));
                    if (!s_m[j]) d2 = 1e10f;
                    unsigned long long key =
                        ((unsigned long long)__float_as_uint(d2) << 32) | (unsigned)j;
                    if (key < curmax) {
                        keys[maxslot] = key;
                        curmax = keys[0]; maxslot = 0;
#pragma unroll
                        for (int k = 1; k < TK; k++)
                            if (keys[k] > curmax) { curmax = keys[k]; maxslot = k; }
                    }
                }
            }
#pragma unroll 1
            for (int r = 0; r < TK; r++) {
                unsigned long long mymin = keys[0]; int mslot = 0;
#pragma unroll
                for (int k = 1; k < TK; k++)
                    if (keys[k] < mymin) { mymin = keys[k]; mslot = k; }
                unsigned long long v = mymin;
#pragma unroll
                for (int off = 16; off; off >>= 1) {
                    unsigned long long o = __shfl_down_sync(0xffffffffu, v, off);
                    if (o < v) v = o;
                }
                v = __shfl_sync(0xffffffffu, v, 0);
                if (v == mymin && v != ~0ULL) keys[mslot] = ~0ULL;
                if (lane == 0) {
                    float d2 = __uint_as_float((unsigned)(v >> 32));
                    int j = (int)(v & 0xffffffffULL);
                    bool valid = (v != ~0ULL) && (d2 < TH2);
                    g_send[node*TK + r] = valid ? j : -1;
                }
            }
        }
        __syncthreads();
    }

    // ======== Phase P: particle encoder + hoisted q ========
    {
        float* w1 = buf;          // 768
        float* w2 = buf + 768;    // 4096
        float* wq = buf + 4864;   // 4096
        float* b1s = buf + 8960;  // 64
        float* b2s = buf + 9024;  // 64
        float* bqs = buf + 9088;  // 64
        float* pin = buf + 9152;  // 48
        float* hb  = buf + 9200;  // 256
        for (int t = tid; t < 12*NF; t += 256) w1[t] = pe_w1[t];
        for (int t = tid; t < NF*NF; t += 256) { w2[t] = pe_w2[t]; wq[t] = pp_w[t]; }
        if (tid < NF) { b1s[tid]=pe_b1[tid]; b2s[tid]=pe_b2[tid]; bqs[tid]=pp_b[tid]; }
        __syncthreads();

        int g = tid >> 6, c = tid & 63;
#pragma unroll 1
        for (int it = 0; it < 8; ++it) {
            int node = node0 + it*4 + g;
            int n = node & (NN-1);
            if (c < 12)
                pin[g*12+c] = (c < 9) ? s_delta[((size_t)bb*9 + c)*NN + n]
                                      : a_cur[bb*NN + n];
            __syncthreads();
            float acc = b1s[c];
#pragma unroll
            for (int r = 0; r < 12; r++) acc = fmaf(pin[g*12+r], w1[r*NF+c], acc);
            hb[g*64+c] = fmaxf(acc, 0.f);
            __syncthreads();
            acc = b2s[c];
#pragma unroll 16
            for (int r = 0; r < NF; r++) acc = fmaf(hb[g*64+r], w2[r*NF+c], acc);
            float pe = fmaxf(acc, 0.f);
            g_eff0[(size_t)node*NF + c] = pe;
            __syncthreads();
            hb[g*64+c] = pe;
            __syncthreads();
            acc = bqs[c];
#pragma unroll 16
            for (int r = 0; r < NF; r++) acc = fmaf(hb[g*64+r], wq[r*NF+c], acc);
            g_q[(size_t)node*NF + c] = acc;
            __syncthreads();
        }
        __syncthreads();
    }

    // ======== Phase R: relation encoder (4 thr/edge, 3 mats resident) ======
    {
        float* sW2 = buf;           // 5120 (64 x stride80, chunk20)
        float* sW3 = buf + 5120;
        float* sWA = buf + 10240;
        float* sw1 = buf + 15360;   // 320
        float* sb1 = buf + 15680;
        float* sb2 = buf + 15744;
        float* sb3 = buf + 15808;
        float* sb4 = buf + 15872;
        float* sh  = buf + 15936;   // 64*132 = 8448 -> end 24384
        for (int t = tid; t < 4096; t += 256) {
            int r = t >> 6, c = t & 63;
            int off = r*80 + (c>>4)*20 + (c&15);
            sW2[off] = re_w2[t];
            sW3[off] = re_w3[t];
            sWA[off] = rp_w[t];
        }
        for (int t = tid; t < 320; t += 256) sw1[t] = re_w1[t];
        if (tid < 64) {
            sb1[tid]=re_b1[tid]; sb2[tid]=re_b2[tid];
            sb3[tid]=re_b3[tid]; sb4[tid]=rp_b[tid];
        }
        __syncthreads();

        int el = tid >> 2, part = tid & 3, cbase = part*16;
        float* myrow = &sh[el*132];
#pragma unroll 1
        for (int pass = 0; pass < 4; pass++) {
            int e = node0*TK + pass*64 + el;
            int node = e >> 3;
            int i = node & (NN-1);
            int j = g_send[e];
            int jj = j < 0 ? 0 : j;

            float rin[5];
            rin[0] = a_cur[bb*NN + i];
            rin[1] = a_cur[bb*NN + jj];
#pragma unroll
            for (int d = 0; d < 3; d++)
                rin[2+d] = states[((size_t)bb*NN + i)*3 + d]
                         - states[((size_t)bb*NN + jj)*3 + d];

            unsigned long long acc2[8];
#pragma unroll
            for (int p = 0; p < 8; p++)
                PACK2(acc2[p], sb1[cbase + 2*p], sb1[cbase + 2*p + 1]);
#pragma unroll
            for (int r = 0; r < 5; r++) {
                unsigned long long xd; DUP2(xd, rin[r]);
                const float* wp = &sw1[r*64 + cbase];
#pragma unroll
                for (int p = 0; p < 8; p++)
                    FMA2(acc2[p], *(const unsigned long long*)(wp + 2*p), xd);
            }
            __syncwarp();
            rel_store_h(myrow, cbase, acc2);
            __syncwarp();

#pragma unroll 1
            for (int L = 0; L < 3; L++) {
                const float* Wm = (L==0) ? sW2 : (L==1) ? sW3 : sWA;
                const float* Bm = (L==0) ? sb2 : (L==1) ? sb3 : sb4;
#pragma unroll
                for (int p = 0; p < 8; p++)
                    PACK2(acc2[p], Bm[cbase + 2*p], Bm[cbase + 2*p + 1]);
#pragma unroll 8
                for (int r = 0; r < 64; r++) {
                    unsigned long long hv =
                        *(const unsigned long long*)(myrow + 2*r);
                    const float* wp = &Wm[r*80 + part*20];
                    ulonglong2 wa = *(const ulonglong2*)(wp);
                    ulonglong2 wb = *(const ulonglong2*)(wp + 4);
                    ulonglong2 wc = *(const ulonglong2*)(wp + 8);
                    ulonglong2 wd = *(const ulonglong2*)(wp + 12);
                    FMA2(acc2[0], wa.x, hv); FMA2(acc2[1], wa.y, hv);
                    FMA2(acc2[2], wb.x, hv); FMA2(acc2[3], wb.y, hv);
                    FMA2(acc2[4], wc.x, hv); FMA2(acc2[5], wc.y, hv);
                    FMA2(acc2[6], wd.x, hv); FMA2(acc2[7], wd.y, hv);
                }
                if (L < 2) {
                    __syncwarp();
                    rel_store_h(myrow, cbase, acc2);
                    __syncwarp();
                } else {
                    float* dst = g_A + (size_t)e*64 + cbase;
#pragma unroll
                    for (int p = 0; p < 4; p++) {
                        float a0,a1,a2,a3;
                        UNPK2(a0, a1, acc2[2*p]);
                        UNPK2(a2, a3, acc2[2*p+1]);
                        if (j < 0) { a0 = a1 = a2 = a3 = 0.f; }
                        *(float4*)(dst + 4*p) = make_float4(a0, a1, a2, a3);
                    }
                    __syncwarp();
                }
            }
        }
        __syncthreads();
    }

    // ======== Phase S: UV0 + 3 fused prop steps ========
    {
        float* sWp  = buf;            // 4096 (pp_w rows 64..127)
        float* sWrs = buf + 4096;     // 12288 ([Wr|Ws] chunk-padded)
        float* sAgg = buf + 16384;    // 64*SA = 4224
        float* sEd  = buf + 20608;    // 64*SED = 4224 -> end 24832
        for (int t = tid; t < 4096; t += 256) sWp[t] = pp_w[4096 + t];
        for (int t = tid; t < 8192; t += 256) {
            int r = t >> 7, c = t & 127;
            float v = (c < 64) ? rp_w[(size_t)(64+r)*64 + c]
                               : rp_w[(size_t)(128+r)*64 + (c-64)];
            sWrs[r*192 + (c>>3)*12 + (c&7)] = v;
        }
        // fill sEd from eff0 (own nodes), duplicated-transposed
        {
            int n = tid >> 3, cg = tid & 7;
            const float* src = g_eff0 + (size_t)(node0 + n)*64 + cg*8;
            float4 v0 = *(const float4*)src;
            float4 v1 = *(const float4*)(src + 4);
            int c = cg*8;
            *(float2*)&sEd[(c+0)*SED + 2*n] = make_float2(v0.x, v0.x);
            *(float2*)&sEd[(c+1)*SED + 2*n] = make_float2(v0.y, v0.y);
            *(float2*)&sEd[(c+2)*SED + 2*n] = make_float2(v0.z, v0.z);
            *(float2*)&sEd[(c+3)*SED + 2*n] = make_float2(v0.w, v0.w);
            *(float2*)&sEd[(c+4)*SED + 2*n] = make_float2(v1.x, v1.x);
            *(float2*)&sEd[(c+5)*SED + 2*n] = make_float2(v1.y, v1.y);
            *(float2*)&sEd[(c+6)*SED + 2*n] = make_float2(v1.z, v1.z);
            *(float2*)&sEd[(c+7)*SED + 2*n] = make_float2(v1.w, v1.w);
        }
        __syncthreads();
        uv_from_sEd(sWrs, sEd, node0, tid);   // UV0
        grid_bar();

#pragma unroll 1
        for (int s = 0; s < 3; s++) {
            const float* effin  = (s & 1) ? g_eff1 : g_eff0;
            float*       effout = (s & 1) ? g_eff0 : g_eff1;

            // --- A1: per-edge gather + relu-sum -> sAgg ---
            int w = tid >> 5, l = tid & 31;
#pragma unroll 1
            for (int kk = 0; kk < 4; kk++) {
                int node = node0 + w*4 + kk;
                int bN = bb * NN;
                float2 u = *(const float2*)&g_UV[(size_t)node*128 + 2*l];
                float s0 = 0.f, s1 = 0.f;
#pragma unroll
                for (int k = 0; k < TK; k++) {
                    int j = g_send[node*TK + k];   // warp-uniform
                    if (j >= 0) {
                        float2 a = *(const float2*)&g_A[((size_t)node*TK + k)*64 + 2*l];
                        float2 v = *(const float2*)&g_UV[(size_t)(bN + j)*128 + 64 + 2*l];
                        s0 += fmaxf(a.x + u.x + v.x, 0.f);
                        s1 += fmaxf(a.y + u.y + v.y, 0.f);
                    }
                }
                int nl = node - node0;
                *(float2*)&sAgg[(2*l  )*SA + 2*nl] = make_float2(s0, s0);
                *(float2*)&sAgg[(2*l+1)*SA + 2*nl] = make_float2(s1, s1);
            }
            __syncthreads();

            // --- A2: effout = relu(effin + q + agg @ Wp1) ; refill sEd ---
            {
                int tc = tid & 31;
                int tn = tid >> 5;
                unsigned long long acc[4] = {0ULL, 0ULL, 0ULL, 0ULL};
#pragma unroll 4
                for (int r = 0; r < 64; r++) {
                    unsigned long long wv =
                        *(const unsigned long long*)&sWp[r*64 + tc*2];
#pragma unroll
                    for (int m = 0; m < 4; m++) {
                        unsigned long long ev =
                            *(const unsigned long long*)&sAgg[r*SA + tn*8 + 2*m];
                        FMA2(acc[m], wv, ev);
                    }
                }
#pragma unroll
                for (int m = 0; m < 4; m++) {
                    int node = node0 + tn*4 + m;
                    int nl = tn*4 + m;
                    float2 ein = *(const float2*)&effin[(size_t)node*64 + 2*tc];
                    float2 q2  = *(const float2*)&g_q  [(size_t)node*64 + 2*tc];
                    float o0, o1; UNPK2(o0, o1, acc[m]);
                    o0 = fmaxf(o0 + ein.x + q2.x, 0.f);
                    o1 = fmaxf(o1 + ein.y + q2.y, 0.f);
                    *(float2*)&effout[(size_t)node*64 + 2*tc] = make_float2(o0, o1);
                    *(float2*)&sEd[(2*tc  )*SED + 2*nl] = make_float2(o0, o0);
                    *(float2*)&sEd[(2*tc+1)*SED + 2*nl] = make_float2(o1, o1);
                }
            }
            if (s < 2) {
                __syncthreads();
                uv_from_sEd(sWrs, sEd, node0, tid);  // UV for next step
                grid_bar();
            }
        }
        __syncthreads();
    }

    // ======== Phase D: predictor + residual add ========
    {
        float* W1 = buf;            // 4096
        float* W2 = buf + 4096;     // 192
        float* b1 = buf + 4288;     // 64
        float* b2 = buf + 4352;     // 3 (+pad)
        float* ef = buf + 4356;     // 256
        float* hh = buf + 4612;     // 256
        for (int t = tid; t < NF*NF; t += 256) W1[t] = pr_w1[t];
        for (int t = tid; t < NF*3;  t += 256) W2[t] = pr_w2[t];
        if (tid < NF) b1[tid] = pr_b1[tid];
        if (tid < 3)  b2[tid] = pr_b2[tid];
        __syncthreads();

        int g = tid >> 6, c = tid & 63;
#pragma unroll 1
        for (int it = 0; it < 8; ++it) {
            int node = node0 + it*4 + g;
            ef[g*64+c] = g_eff1[(size_t)node*NF + c];
            __syncthreads();
            float acc = b1[c];
#pragma unroll 16
            for (int r = 0; r < NF; r++) acc = fmaf(ef[g*64+r], W1[r*NF+c], acc);
            hh[g*64+c] = fmaxf(acc, 0.f);
            __syncthreads();
            if (c < 3) {
                float p = b2[c];
#pragma unroll 16
                for (int r = 0; r < NF; r++) p = fmaf(hh[g*64+r], W2[r*3+c], p);
                out[(size_t)node*3 + c] = states[(size_t)node*3 + c] + p;
            }
            __syncthreads();
        }
    }
}

// ---------------- launch ----------------
extern "C" void kernel_launch(void* const* d_in, const int* in_sizes, int n_in,
                              void* d_out, int out_size)
{
    const float* states  = (const float*)d_in[0];
    const float* a_cur   = (const float*)d_in[1];
    const float* s_delta = (const float*)d_in[2];
    const unsigned char* mask  = (const unsigned char*)d_in[3];
    const unsigned char* tmask = (const unsigned char*)d_in[4];
    int wbase = (n_in > 5 && in_sizes[5] == 1) ? 6 : 5;
    const float* pe_w1 = (const float*)d_in[wbase + 0];
    const float* pe_b1 = (const float*)d_in[wbase + 1];
    const float* pe_w2 = (const float*)d_in[wbase + 2];
    const float* pe_b2 = (const float*)d_in[wbase + 3];
    const float* re_w1 = (const float*)d_in[wbase + 4];
    const float* re_b1 = (const float*)d_in[wbase + 5];
    const float* re_w2 = (const float*)d_in[wbase + 6];
    const float* re_b2 = (const float*)d_in[wbase + 7];
    const float* re_w3 = (const float*)d_in[wbase + 8];
    const float* re_b3 = (const float*)d_in[wbase + 9];
    const float* rp_w  = (const float*)d_in[wbase + 10];
    const float* rp_b  = (const float*)d_in[wbase + 11];
    const float* pp_w  = (const float*)d_in[wbase + 12];
    const float* pp_b  = (const float*)d_in[wbase + 13];
    const float* pr_w1 = (const float*)d_in[wbase + 14];
    const float* pr_b1 = (const float*)d_in[wbase + 15];
    const float* pr_w2 = (const float*)d_in[wbase + 16];
    const float* pr_b2 = (const float*)d_in[wbase + 17];
    float* out = (float*)d_out;

    const int DSM = 24832 * 4;   // 99328 B
    static int attr_done = 0;
    if (!attr_done) {
        cudaFuncSetAttribute(k_all, cudaFuncAttributeMaxDynamicSharedMemorySize, DSM);
        attr_done = 1;
    }

    k_all<<<NBLK, 256, DSM>>>(states, a_cur, s_delta, mask, tmask,
                              pe_w1, pe_b1, pe_w2, pe_b2,
                              re_w1, re_b1, re_w2, re_b2, re_w3, re_b3,
                              rp_w, rp_b, pp_w, pp_b,
                              pr_w1, pr_b1, pr_w2, pr_b2, out);
}

// round 8
// speedup vs baseline: 1.3321x; 1.0463x over previous
#include <cuda_runtime.h>
#include <stdint.h>

#define BB 2
#define NN 2048
#define TK 8
#define NF 64
#define NNODES (BB*NN)
#define NE (NNODES*TK)
#define NBLK 128
#define NT 512
#define SED 66
#define SA  66

// ---------------- packed-fp32 (FFMA2) helpers ----------------
#define FMA2(acc, a, b) \
    asm("fma.rn.f32x2 %0, %1, %2, %0;" : "+l"(acc) : "l"(a), "l"(b))
#define DUP2(d, v) \
    asm("mov.b64 %0, {%1, %1};" : "=l"(d) : "f"(v))
#define PACK2(d, lo, hi) \
    asm("mov.b64 %0, {%1, %2};" : "=l"(d) : "f"(lo), "f"(hi))
#define UNPK2(lo, hi, v) \
    asm("mov.b64 {%0, %1}, %2;" : "=f"(lo), "=f"(hi) : "l"(v))

// ---------------- device scratch ----------------
__device__ int   g_send[NE];
__device__ float g_A[NE*NF];
__device__ float g_q[NNODES*NF];
__device__ float g_UV[NNODES*128];
__device__ float g_eff0[NNODES*NF];
__device__ float g_eff1[NNODES*NF];
__device__ unsigned g_bar_cnt = 0;
__device__ unsigned g_bar_gen = 0;

// mask dtype detection (mask[0] true in-dataset)
__device__ __forceinline__ unsigned char mask_elem(const unsigned char* p, int i) {
    unsigned w0 = *(const unsigned*)p;
    if (w0 == 0x01010101u) return p[i] != 0;
    if (w0 == 0x3f800000u) return ((const float*)p)[i] != 0.f;
    return ((const int*)p)[i] != 0;
}

// grid-wide barrier: all NBLK blocks wave-1 resident (NBLK <= 148 SMs).
__device__ __forceinline__ void grid_bar() {
    __threadfence();
    __syncthreads();
    if (threadIdx.x == 0) {
        volatile unsigned* genp = &g_bar_gen;
        unsigned gen = *genp;
        if (atomicInc(&g_bar_cnt, NBLK - 1) == NBLK - 1) {
            atomicAdd(&g_bar_gen, 1);
        } else {
            while (*genp == gen) { }
        }
    }
    __syncthreads();
    __threadfence();
}

// h-chunk store for rel phase (row private to a 4-thread quad)
__device__ __forceinline__ void rel_store_h(
    float* myrow, int cbase, const unsigned long long* acc2)
{
#pragma unroll
    for (int p = 0; p < 4; p++) {
        float a0,a1,a2,a3;
        UNPK2(a0, a1, acc2[2*p]);
        UNPK2(a2, a3, acc2[2*p+1]);
        a0 = fmaxf(a0, 0.f); a1 = fmaxf(a1, 0.f);
        a2 = fmaxf(a2, 0.f); a3 = fmaxf(a3, 0.f);
        float* dst = myrow + 2*cbase + 8*p;
        *(float4*)dst       = make_float4(a0, a0, a1, a1);
        *(float4*)(dst + 4) = make_float4(a2, a2, a3, a3);
    }
}

// UV' = sEd(dup,transposed eff) @ [Wr|Ws] -> g_UV (own 32 nodes, 1 node/thread)
__device__ __forceinline__ void uv_from_sEd(
    const float* sWrs, const float* sEd, int node0, int tid)
{
    int tc2 = tid & 15;   // 8 cols of 128
    int tn2 = tid >> 4;   // 0..31, one node
    unsigned long long acc[4] = {0ULL, 0ULL, 0ULL, 0ULL};
#pragma unroll 8
    for (int r = 0; r < 64; r++) {
        unsigned long long ev = *(const unsigned long long*)&sEd[r*SED + 2*tn2];
        const float* wp = &sWrs[r*192 + tc2*12];
        ulonglong2 wa = *(const ulonglong2*)(wp);
        ulonglong2 wb = *(const ulonglong2*)(wp + 4);
        FMA2(acc[0], wa.x, ev); FMA2(acc[1], wa.y, ev);
        FMA2(acc[2], wb.x, ev); FMA2(acc[3], wb.y, ev);
    }
    int node = node0 + tn2;
    float x0,x1,x2,x3,x4,x5,x6,x7;
    UNPK2(x0,x1, acc[0]); UNPK2(x2,x3, acc[1]);
    UNPK2(x4,x5, acc[2]); UNPK2(x6,x7, acc[3]);
    float* dst = g_UV + (size_t)node*128 + tc2*8;
    *(float4*)dst       = make_float4(x0,x1,x2,x3);
    *(float4*)(dst + 4) = make_float4(x4,x5,x6,x7);
}

// =====================  THE persistent kernel  =====================
__global__ __launch_bounds__(NT) void k_all(
    const float* __restrict__ states, const float* __restrict__ a_cur,
    const float* __restrict__ s_delta,
    const unsigned char* __restrict__ mask_raw,
    const unsigned char* __restrict__ tmask_raw,
    const float* __restrict__ pe_w1, const float* __restrict__ pe_b1,
    const float* __restrict__ pe_w2, const float* __restrict__ pe_b2,
    const float* __restrict__ re_w1, const float* __restrict__ re_b1,
    const float* __restrict__ re_w2, const float* __restrict__ re_b2,
    const float* __restrict__ re_w3, const float* __restrict__ re_b3,
    const float* __restrict__ rp_w,  const float* __restrict__ rp_b,
    const float* __restrict__ pp_w,  const float* __restrict__ pp_b,
    const float* __restrict__ pr_w1, const float* __restrict__ pr_b1,
    const float* __restrict__ pr_w2, const float* __restrict__ pr_b2,
    float* __restrict__ out)
{
    extern __shared__ float buf[];
    const int tid = threadIdx.x;
    const int node0 = blockIdx.x * 32;     // 32 owned nodes (same batch)
    const int bb = node0 >> 11;
    const int i0 = node0 & (NN-1);

    // ======== Phase E: edge construction (8-NN + threshold) ========
    {
        float* s_st = buf;                                    // 6144
        unsigned char* s_m = (unsigned char*)(buf + 6144);    // 2048 B
        const float* stb = states + (size_t)bb*NN*3;
        for (int t = tid; t < NN*3; t += NT) s_st[t] = stb[t];
        for (int t = tid; t < NN;   t += NT)
            s_m[t] = mask_elem(mask_raw, bb*NN + t);
        __syncthreads();

        const float TH2 = 0.12f * 0.12f;
        int w = tid >> 5, lane = tid & 31;   // w in 0..15
#pragma unroll 1
        for (int sub = 0; sub < 2; sub++) {
            int i = i0 + sub*16 + w;
            int node = bb*NN + i;
            bool recv_ok = (s_m[i] != 0) && !mask_elem(tmask_raw, node);

            unsigned long long keys[TK];
#pragma unroll
            for (int k = 0; k < TK; k++) keys[k] = ~0ULL;

            if (recv_ok) {
                float xi = s_st[i*3+0], yi = s_st[i*3+1], zi = s_st[i*3+2];
                unsigned long long curmax = ~0ULL; int maxslot = 0;
                for (int j = lane; j < NN; j += 32) {
                    float dx = xi - s_st[j*3+0];
                    float dy = yi - s_st[j*3+1];
                    float dz = zi - s_st[j*3+2];
                    float d2 = fmaf(dx, dx, fmaf(dy, dy, dz*dz));
                    if (!s_m[j]) d2 = 1e10f;
                    unsigned long long key =
                        ((unsigned long long)__float_as_uint(d2) << 32) | (unsigned)j;
                    if (key < curmax) {
                        keys[maxslot] = key;
                        curmax = keys[0]; maxslot = 0;
#pragma unroll
                        for (int k = 1; k < TK; k++)
                            if (keys[k] > curmax) { curmax = keys[k]; maxslot = k; }
                    }
                }
            }
#pragma unroll 1
            for (int r = 0; r < TK; r++) {
                unsigned long long mymin = keys[0]; int mslot = 0;
#pragma unroll
                for (int k = 1; k < TK; k++)
                    if (keys[k] < mymin) { mymin = keys[k]; mslot = k; }
                unsigned long long v = mymin;
#pragma unroll
                for (int off = 16; off; off >>= 1) {
                    unsigned long long o = __shfl_down_sync(0xffffffffu, v, off);
                    if (o < v) v = o;
                }
                v = __shfl_sync(0xffffffffu, v, 0);
                if (v == mymin && v != ~0ULL) keys[mslot] = ~0ULL;
                if (lane == 0) {
                    float d2 = __uint_as_float((unsigned)(v >> 32));
                    int j = (int)(v & 0xffffffffULL);
                    bool valid = (v != ~0ULL) && (d2 < TH2);
                    g_send[node*TK + r] = valid ? j : -1;
                }
            }
        }
        __syncthreads();
    }

    // ======== Phase P: particle encoder + hoisted q ========
    {
        float* w1 = buf;          // 768
        float* w2 = buf + 768;    // 4096
        float* wq = buf + 4864;   // 4096
        float* b1s = buf + 8960;  // 64
        float* b2s = buf + 9024;  // 64
        float* bqs = buf + 9088;  // 64
        float* pin = buf + 9152;  // 96  (8 groups x 12)
        float* hb  = buf + 9248;  // 512 (8 groups x 64)
        for (int t = tid; t < 12*NF; t += NT) w1[t] = pe_w1[t];
        for (int t = tid; t < NF*NF; t += NT) { w2[t] = pe_w2[t]; wq[t] = pp_w[t]; }
        if (tid < NF) { b1s[tid]=pe_b1[tid]; b2s[tid]=pe_b2[tid]; bqs[tid]=pp_b[tid]; }
        __syncthreads();

        int g = tid >> 6, c = tid & 63;   // g in 0..7
#pragma unroll 1
        for (int it = 0; it < 4; ++it) {
            int node = node0 + it*8 + g;
            int n = node & (NN-1);
            if (c < 12)
                pin[g*12+c] = (c < 9) ? s_delta[((size_t)bb*9 + c)*NN + n]
                                      : a_cur[bb*NN + n];
            __syncthreads();
            float acc = b1s[c];
#pragma unroll
            for (int r = 0; r < 12; r++) acc = fmaf(pin[g*12+r], w1[r*NF+c], acc);
            hb[g*64+c] = fmaxf(acc, 0.f);
            __syncthreads();
            acc = b2s[c];
#pragma unroll 16
            for (int r = 0; r < NF; r++) acc = fmaf(hb[g*64+r], w2[r*NF+c], acc);
            float pe = fmaxf(acc, 0.f);
            g_eff0[(size_t)node*NF + c] = pe;
            __syncthreads();
            hb[g*64+c] = pe;
            __syncthreads();
            acc = bqs[c];
#pragma unroll 16
            for (int r = 0; r < NF; r++) acc = fmaf(hb[g*64+r], wq[r*NF+c], acc);
            g_q[(size_t)node*NF + c] = acc;
            __syncthreads();
        }
        __syncthreads();
    }

    // ======== Phase R: relation encoder (4 thr/edge, 128 edges/pass) ======
    {
        float* sW2 = buf;           // 5120 (64 x stride80, chunk20)
        float* sW3 = buf + 5120;
        float* sWA = buf + 10240;
        float* sw1 = buf + 15360;   // 320
        float* sb1 = buf + 15680;
        float* sb2 = buf + 15744;
        float* sb3 = buf + 15808;
        float* sb4 = buf + 15872;
        float* sh  = buf + 15936;   // 128*132 = 16896 -> end 32832
        for (int t = tid; t < 4096; t += NT) {
            int r = t >> 6, c = t & 63;
            int off = r*80 + (c>>4)*20 + (c&15);
            sW2[off] = re_w2[t];
            sW3[off] = re_w3[t];
            sWA[off] = rp_w[t];
        }
        for (int t = tid; t < 320; t += NT) sw1[t] = re_w1[t];
        if (tid < 64) {
            sb1[tid]=re_b1[tid]; sb2[tid]=re_b2[tid];
            sb3[tid]=re_b3[tid]; sb4[tid]=rp_b[tid];
        }
        __syncthreads();

        int el = tid >> 2, part = tid & 3, cbase = part*16;  // el in 0..127
        float* myrow = &sh[el*132];
#pragma unroll 1
        for (int pass = 0; pass < 2; pass++) {
            int e = node0*TK + pass*128 + el;
            int node = e >> 3;
            int i = node & (NN-1);
            int j = g_send[e];
            int jj = j < 0 ? 0 : j;

            float rin[5];
            rin[0] = a_cur[bb*NN + i];
            rin[1] = a_cur[bb*NN + jj];
#pragma unroll
            for (int d = 0; d < 3; d++)
                rin[2+d] = states[((size_t)bb*NN + i)*3 + d]
                         - states[((size_t)bb*NN + jj)*3 + d];

            unsigned long long acc2[8];
#pragma unroll
            for (int p = 0; p < 8; p++)
                PACK2(acc2[p], sb1[cbase + 2*p], sb1[cbase + 2*p + 1]);
#pragma unroll
            for (int r = 0; r < 5; r++) {
                unsigned long long xd; DUP2(xd, rin[r]);
                const float* wp = &sw1[r*64 + cbase];
#pragma unroll
                for (int p = 0; p < 8; p++)
                    FMA2(acc2[p], *(const unsigned long long*)(wp + 2*p), xd);
            }
            __syncwarp();
            rel_store_h(myrow, cbase, acc2);
            __syncwarp();

#pragma unroll 1
            for (int L = 0; L < 3; L++) {
                const float* Wm = (L==0) ? sW2 : (L==1) ? sW3 : sWA;
                const float* Bm = (L==0) ? sb2 : (L==1) ? sb3 : sb4;
#pragma unroll
                for (int p = 0; p < 8; p++)
                    PACK2(acc2[p], Bm[cbase + 2*p], Bm[cbase + 2*p + 1]);
#pragma unroll 8
                for (int r = 0; r < 64; r++) {
                    unsigned long long hv =
                        *(const unsigned long long*)(myrow + 2*r);
                    const float* wp = &Wm[r*80 + part*20];
                    ulonglong2 wa = *(const ulonglong2*)(wp);
                    ulonglong2 wb = *(const ulonglong2*)(wp + 4);
                    ulonglong2 wc = *(const ulonglong2*)(wp + 8);
                    ulonglong2 wd = *(const ulonglong2*)(wp + 12);
                    FMA2(acc2[0], wa.x, hv); FMA2(acc2[1], wa.y, hv);
                    FMA2(acc2[2], wb.x, hv); FMA2(acc2[3], wb.y, hv);
                    FMA2(acc2[4], wc.x, hv); FMA2(acc2[5], wc.y, hv);
                    FMA2(acc2[6], wd.x, hv); FMA2(acc2[7], wd.y, hv);
                }
                if (L < 2) {
                    __syncwarp();
                    rel_store_h(myrow, cbase, acc2);
                    __syncwarp();
                } else {
                    float* dst = g_A + (size_t)e*64 + cbase;
#pragma unroll
                    for (int p = 0; p < 4; p++) {
                        float a0,a1,a2,a3;
                        UNPK2(a0, a1, acc2[2*p]);
                        UNPK2(a2, a3, acc2[2*p+1]);
                        if (j < 0) { a0 = a1 = a2 = a3 = 0.f; }
                        *(float4*)(dst + 4*p) = make_float4(a0, a1, a2, a3);
                    }
                    __syncwarp();
                }
            }
        }
        __syncthreads();
    }

    // ======== Phase S: UV0 + 3 fused prop steps ========
    {
        float* sWp  = buf;            // 4096 (pp_w rows 64..127)
        float* sWrs = buf + 4096;     // 12288 ([Wr|Ws] chunk-padded)
        float* sAgg = buf + 16384;    // 64*SA = 4224
        float* sEd  = buf + 20608;    // 64*SED = 4224 -> end 24832
        for (int t = tid; t < 4096; t += NT) sWp[t] = pp_w[4096 + t];
        for (int t = tid; t < 8192; t += NT) {
            int r = t >> 7, c = t & 127;
            float v = (c < 64) ? rp_w[(size_t)(64+r)*64 + c]
                               : rp_w[(size_t)(128+r)*64 + (c-64)];
            sWrs[r*192 + (c>>3)*12 + (c&7)] = v;
        }
        // fill sEd from eff0 (own nodes), duplicated-transposed
        {
            int n = tid >> 4, cg = tid & 15;   // n 0..31, 4 cols each
            const float* src = g_eff0 + (size_t)(node0 + n)*64 + cg*4;
            float4 v = *(const float4*)src;
            int c = cg*4;
            *(float2*)&sEd[(c+0)*SED + 2*n] = make_float2(v.x, v.x);
            *(float2*)&sEd[(c+1)*SED + 2*n] = make_float2(v.y, v.y);
            *(float2*)&sEd[(c+2)*SED + 2*n] = make_float2(v.z, v.z);
            *(float2*)&sEd[(c+3)*SED + 2*n] = make_float2(v.w, v.w);
        }
        __syncthreads();
        uv_from_sEd(sWrs, sEd, node0, tid);   // UV0
        grid_bar();

#pragma unroll 1
        for (int s = 0; s < 3; s++) {
            const float* effin  = (s & 1) ? g_eff1 : g_eff0;
            float*       effout = (s & 1) ? g_eff0 : g_eff1;

            // --- A1: per-edge gather + relu-sum -> sAgg ---
            int w = tid >> 5, l = tid & 31;   // w 0..15
#pragma unroll 1
            for (int kk = 0; kk < 2; kk++) {
                int node = node0 + w*2 + kk;
                int bN = bb * NN;
                float2 u = *(const float2*)&g_UV[(size_t)node*128 + 2*l];
                float s0 = 0.f, s1 = 0.f;
#pragma unroll
                for (int k = 0; k < TK; k++) {
                    int j = g_send[node*TK + k];   // warp-uniform
                    if (j >= 0) {
                        float2 a = *(const float2*)&g_A[((size_t)node*TK + k)*64 + 2*l];
                        float2 v = *(const float2*)&g_UV[(size_t)(bN + j)*128 + 64 + 2*l];
                        s0 += fmaxf(a.x + u.x + v.x, 0.f);
                        s1 += fmaxf(a.y + u.y + v.y, 0.f);
                    }
                }
                int nl = node - node0;
                *(float2*)&sAgg[(2*l  )*SA + 2*nl] = make_float2(s0, s0);
                *(float2*)&sAgg[(2*l+1)*SA + 2*nl] = make_float2(s1, s1);
            }
            __syncthreads();

            // --- A2: effout = relu(effin + q + agg @ Wp1) ; refill sEd ---
            {
                int tc = tid & 31;   // 2 cols
                int tn = tid >> 5;   // 0..15, 2 nodes each
                unsigned long long acc[2] = {0ULL, 0ULL};
#pragma unroll 4
                for (int r = 0; r < 64; r++) {
                    unsigned long long wv =
                        *(const unsigned long long*)&sWp[r*64 + tc*2];
#pragma unroll
                    for (int m = 0; m < 2; m++) {
                        unsigned long long ev =
                            *(const unsigned long long*)&sAgg[r*SA + tn*4 + 2*m];
                        FMA2(acc[m], wv, ev);
                    }
                }
#pragma unroll
                for (int m = 0; m < 2; m++) {
                    int node = node0 + tn*2 + m;
                    int nl = tn*2 + m;
                    float2 ein = *(const float2*)&effin[(size_t)node*64 + 2*tc];
                    float2 q2  = *(const float2*)&g_q  [(size_t)node*64 + 2*tc];
                    float o0, o1; UNPK2(o0, o1, acc[m]);
                    o0 = fmaxf(o0 + ein.x + q2.x, 0.f);
                    o1 = fmaxf(o1 + ein.y + q2.y, 0.f);
                    *(float2*)&effout[(size_t)node*64 + 2*tc] = make_float2(o0, o1);
                    *(float2*)&sEd[(2*tc  )*SED + 2*nl] = make_float2(o0, o0);
                    *(float2*)&sEd[(2*tc+1)*SED + 2*nl] = make_float2(o1, o1);
                }
            }
            if (s < 2) {
                __syncthreads();
                uv_from_sEd(sWrs, sEd, node0, tid);  // UV for next step
                grid_bar();
            }
        }
        __syncthreads();
    }

    // ======== Phase D: predictor + residual add ========
    {
        float* W1 = buf;            // 4096
        float* W2 = buf + 4096;     // 192
        float* b1 = buf + 4288;     // 64
        float* b2 = buf + 4352;     // 4 (pad)
        float* ef = buf + 4356;     // 512
        float* hh = buf + 4868;     // 512
        for (int t = tid; t < NF*NF; t += NT) W1[t] = pr_w1[t];
        for (int t = tid; t < NF*3;  t += NT) W2[t] = pr_w2[t];
        if (tid < NF) b1[tid] = pr_b1[tid];
        if (tid < 3)  b2[tid] = pr_b2[tid];
        __syncthreads();

        int g = tid >> 6, c = tid & 63;   // g 0..7
#pragma unroll 1
        for (int it = 0; it < 4; ++it) {
            int node = node0 + it*8 + g;
            ef[g*64+c] = g_eff1[(size_t)node*NF + c];
            __syncthreads();
            float acc = b1[c];
#pragma unroll 16
            for (int r = 0; r < NF; r++) acc = fmaf(ef[g*64+r], W1[r*NF+c], acc);
            hh[g*64+c] = fmaxf(acc, 0.f);
            __syncthreads();
            if (c < 3) {
                float p = b2[c];
#pragma unroll 16
                for (int r = 0; r < NF; r++) p = fmaf(hh[g*64+r], W2[r*3+c], p);
                out[(size_t)node*3 + c] = states[(size_t)node*3 + c] + p;
            }
            __syncthreads();
        }
    }
}

// ---------------- launch ----------------
extern "C" void kernel_launch(void* const* d_in, const int* in_sizes, int n_in,
                              void* d_out, int out_size)
{
    const float* states  = (const float*)d_in[0];
    const float* a_cur   = (const float*)d_in[1];
    const float* s_delta = (const float*)d_in[2];
    const unsigned char* mask  = (const unsigned char*)d_in[3];
    const unsigned char* tmask = (const unsigned char*)d_in[4];
    int wbase = (n_in > 5 && in_sizes[5] == 1) ? 6 : 5;
    const float* pe_w1 = (const float*)d_in[wbase + 0];
    const float* pe_b1 = (const float*)d_in[wbase + 1];
    const float* pe_w2 = (const float*)d_in[wbase + 2];
    const float* pe_b2 = (const float*)d_in[wbase + 3];
    const float* re_w1 = (const float*)d_in[wbase + 4];
    const float* re_b1 = (const float*)d_in[wbase + 5];
    const float* re_w2 = (const float*)d_in[wbase + 6];
    const float* re_b2 = (const float*)d_in[wbase + 7];
    const float* re_w3 = (const float*)d_in[wbase + 8];
    const float* re_b3 = (const float*)d_in[wbase + 9];
    const float* rp_w  = (const float*)d_in[wbase + 10];
    const float* rp_b  = (const float*)d_in[wbase + 11];
    const float* pp_w  = (const float*)d_in[wbase + 12];
    const float* pp_b  = (const float*)d_in[wbase + 13];
    const float* pr_w1 = (const float*)d_in[wbase + 14];
    const float* pr_b1 = (const float*)d_in[wbase + 15];
    const float* pr_w2 = (const float*)d_in[wbase + 16];
    const float* pr_b2 = (const float*)d_in[wbase + 17];
    float* out = (float*)d_out;

    const int DSM = 32832 * 4;   // 131328 B (phase R peak)
    static int attr_done = 0;
    if (!attr_done) {
        cudaFuncSetAttribute(k_all, cudaFuncAttributeMaxDynamicSharedMemorySize, DSM);
        attr_done = 1;
    }

    k_all<<<NBLK, NT, DSM>>>(states, a_cur, s_delta, mask, tmask,
                             pe_w1, pe_b1, pe_w2, pe_b2,
                             re_w1, re_b1, re_w2, re_b2, re_w3, re_b3,
                             rp_w, rp_b, pp_w, pp_b,
                             pr_w1, pr_b1, pr_w2, pr_b2, out);
}